// round 9
// baseline (speedup 1.0000x reference)
#include <cuda_runtime.h>

// Depth-5 path signature, B=256, d=10, L=128 (127 segments).
// Output row: [S1(10) | S2(100) | S3(1000) | S4(10000) | S5(100000)] = 111110 floats.
//
// Chen recurrence with rank-1 segment tensors (increment δ):
//   P3[abc] = S3/2 + δc*(S2/6 + δb*(S1/24 + δa/120))
//   Y3[abc] = S3   + δc*(S2/2 + δb*(S1/6  + δa/24))
//   X4[abcd] = S4[abcd] + δd*P3[abc];  S4 += Y3 ⊗ δ;  S5 += X4 ⊗ δ
//   S3 += δc*(S2 + δb*(S1/2 + δa/6));  S2 += δb*(S1 + δa/2);  S1 += δ
//
// CTA = (batch b, a-pair j), 200 threads, thread = one abc, owns all 10 d.
// R8: target 2 CTAs/SM (3.5 warps/SMSP) — launch_bounds(200,2) gives a 144-reg
// cap; the body is trimmed (no pipeline regs, d-pairs loaded at use, e-broadcasts
// via LDS.128 pairs) so the live set fits without spilling. Latency hiding now
// comes from TLP instead of the failed single-warp software pipeline (R7:
// issue 41.5% at 1.75 warps/SMSP).

#define NB 256
#define DCH 10
#define LEN 128
#define NSEG 127
#define THREADS 200
#define ROW 111110
#define APAD 12      // sdA row stride (floats): 48B rows, 16B-aligned
#define BPAD 12      // sdB row stride (ulls): 96B rows, 16B-aligned

typedef unsigned long long ull;

__device__ __forceinline__ ull pk(float lo, float hi) {
    ull r;
    asm("mov.b64 %0, {%1, %2};" : "=l"(r) : "f"(lo), "f"(hi));
    return r;
}
__device__ __forceinline__ void upk(ull v, float& lo, float& hi) {
    asm("mov.b64 {%0, %1}, %2;" : "=f"(lo), "=f"(hi) : "l"(v));
}
__device__ __forceinline__ ull ffma2(ull a, ull b, ull c) {
    ull d;
    asm("fma.rn.f32x2 %0, %1, %2, %3;" : "=l"(d) : "l"(a), "l"(b), "l"(c));
    return d;
}

__global__ __launch_bounds__(THREADS, 2)
void sig_kernel(const float* __restrict__ path, float* __restrict__ out) {
    __shared__ __align__(16) float sdA[NSEG * APAD];  // [t][c] scalar deltas
    __shared__ __align__(16) ull   sdB[NSEG * BPAD];  // [t][e] = (δe, δe) pairs

    const int tid = threadIdx.x;
    const int b   = blockIdx.x / 5;
    const int j   = blockIdx.x % 5;

    // ---- segment increments into both SMEM layouts ----
    const float* pb = path + b * (DCH * LEN);
    for (int idx = tid; idx < NSEG * DCH; idx += THREADS) {
        int c = idx / NSEG, t = idx % NSEG;
        float d = pb[c * LEN + t + 1] - pb[c * LEN + t];
        sdA[t * APAD + c] = d;
        sdB[t * BPAD + c] = pk(d, d);
    }
    __syncthreads();

    const int half = tid / 100;        // a = 2j + half
    const int a    = 2 * j + half;
    const int bc   = tid % 100;
    const int hb   = bc / 10;
    const int hc   = bc % 10;

    float s1 = 0.f, s2 = 0.f, s3 = 0.f;   // private S1[a], S2[ab], S3[abc]
    ull s4p[5];                            // [i] = (S4[abc,2i], S4[abc,2i+1])
    ull s5[5][10];                         // [i][e] = (S5[abc,2i,e], S5[abc,2i+1,e])
#pragma unroll
    for (int i = 0; i < 5; ++i) {
        s4p[i] = 0ull;
#pragma unroll
        for (int e = 0; e < 10; ++e) s5[i][e] = 0ull;
    }

    const float* dl = sdA;
    const ull*   bl = sdB;
    for (int t = 0; t < NSEG; ++t, dl += APAD, bl += BPAD) {
        // scalar deltas for the Horner chains (issued first; latency overlaps below)
        float da = dl[a], db = dl[hb], dc = dl[hc];

        // Horner chains + private state update
        float P1 = fmaf(da, 1.f / 120.f, s1 * (1.f / 24.f));
        float P2 = fmaf(db, P1, s2 * (1.f / 6.f));
        float P3 = fmaf(dc, P2, s3 * 0.5f);
        float Q1 = fmaf(da, 1.f / 24.f, s1 * (1.f / 6.f));
        float Q2 = fmaf(db, Q1, s2 * 0.5f);
        float Y3 = fmaf(dc, Q2, s3);
        float Z1 = fmaf(da, 1.f / 6.f, s1 * 0.5f);
        float Z2 = fmaf(db, Z1, s2);
        s3 = fmaf(dc, Z2, s3);
        float W1 = fmaf(da, 0.5f, s1);
        s2 = fmaf(db, W1, s2);
        s1 += da;

        ull P3p = pk(P3, P3), Y3p = pk(Y3, Y3);

        // X4 / S4, d-pairs loaded at use (LDS.64, 8B-aligned: offsets 0,8,16,24,32B)
        ull Xp[5];
#pragma unroll
        for (int i = 0; i < 5; ++i) {
            ull ep = *(const ull*)(dl + 2 * i);
            Xp[i]  = ffma2(ep, P3p, s4p[i]);
            s4p[i] = ffma2(ep, Y3p, s4p[i]);
        }

        // S5: e-broadcasts two-at-a-time via LDS.128 (rows 16B-aligned)
#pragma unroll
        for (int q = 0; q < 5; ++q) {
            ulonglong2 ebp = *(const ulonglong2*)(bl + 2 * q);  // (δ2q,δ2q) (δ2q+1,δ2q+1)
#pragma unroll
            for (int i = 0; i < 5; ++i)
                s5[i][2 * q]     = ffma2(Xp[i], ebp.x, s5[i][2 * q]);
#pragma unroll
            for (int i = 0; i < 5; ++i)
                s5[i][2 * q + 1] = ffma2(Xp[i], ebp.y, s5[i][2 * q + 1]);
        }
    }

    // ---- epilogue ----
    float* orow = out + (size_t)b * ROW;
    const int abc = a * 100 + bc;
    if (bc == 0) orow[a] = s1;
    if (hc == 0) orow[10 + a * 10 + hb] = s2;
    orow[110 + abc] = s3;

    ull* o4 = (ull*)(orow + 1110 + abc * 10);   // even float offset -> STG.64 ok
#pragma unroll
    for (int i = 0; i < 5; ++i) o4[i] = s4p[i];

    // S5: s5[i][e] lanes are rows d=2i and d=2i+1 of this abc's 100-float block.
    float* o5 = orow + 11110 + abc * 100;
#pragma unroll
    for (int i = 0; i < 5; ++i) {
        ull* r0 = (ull*)(o5 + 20 * i);        // row d=2i   (8B-aligned)
        ull* r1 = (ull*)(o5 + 20 * i + 10);   // row d=2i+1
#pragma unroll
        for (int p = 0; p < 5; ++p) {
            float l0, h0, l1, h1;
            upk(s5[i][2 * p],     l0, h0);
            upk(s5[i][2 * p + 1], l1, h1);
            r0[p] = pk(l0, l1);
            r1[p] = pk(h0, h1);
        }
    }
}

extern "C" void kernel_launch(void* const* d_in, const int* in_sizes, int n_in,
                              void* d_out, int out_size) {
    const float* path = (const float*)d_in[0];  // (256, 10, 128) fp32
    float* out = (float*)d_out;                 // (256, 111110) fp32
    sig_kernel<<<NB * 5, THREADS>>>(path, out);
}

// round 10
// speedup vs baseline: 1.1550x; 1.1550x over previous
#include <cuda_runtime.h>

// Depth-5 path signature, B=256, d=10, L=128 (127 segments).
// Output row: [S1(10) | S2(100) | S3(1000) | S4(10000) | S5(100000)] = 111110 floats.
//
// Chen recurrence with rank-1 segment tensors (increment δ):
//   P3[abc] = S3/2 + δc*(S2/6 + δb*(S1/24 + δa/120))
//   Y3[abc] = S3   + δc*(S2/2 + δb*(S1/6  + δa/24))
//   X4[abcd] = S4[abcd] + δd*P3[abc];  S4 += Y3 ⊗ δ;  S5 += X4 ⊗ δ
//   S3 += δc*(S2 + δb*(S1/2 + δa/6));  S2 += δb*(S1 + δa/2);  S1 += δ
//
// R10 geometry fix over R3 (238us): same per-thread structure (5 interleaved
// d-columns, 25 packed S5 f32x2 + 5 S4 scalars, ~80 regs, zero barriers), but
// CTA = 800 threads = (2 batches x 2 a-values) = EXACTLY 25 warps:
//   - 0% dead lanes (R3: 200 thr -> 7 warps, 10.7% waste)
//   - 25 warps/SM = 6.25/SMSP (R3: 21), reg file 25*32*81 = 64800/65536
//   - grid 640 -> 4.3 waves (R3: 5.8)

#define NB 256
#define DCH 10
#define LEN 128
#define NSEG 127
#define THREADS 800
#define ROW 111110
#define APAD 12   // sdA row stride: 48B rows, 16B-aligned

typedef unsigned long long ull;

__device__ __forceinline__ ull pk(float lo, float hi) {
    ull r;
    asm("mov.b64 %0, {%1, %2};" : "=l"(r) : "f"(lo), "f"(hi));
    return r;
}
__device__ __forceinline__ void upk(ull v, float& lo, float& hi) {
    asm("mov.b64 {%0, %1}, %2;" : "=f"(lo), "=f"(hi) : "l"(v));
}
__device__ __forceinline__ ull ffma2(ull a, ull b, ull c) {
    ull d;
    asm("fma.rn.f32x2 %0, %1, %2, %3;" : "=l"(d) : "l"(a), "l"(b), "l"(c));
    return d;
}

__global__ __launch_bounds__(THREADS, 1)
void sig_kernel(const float* __restrict__ path, float* __restrict__ out) {
    __shared__ __align__(16) float sdA[2][NSEG * APAD];  // [bsel][t][c]

    const int tid = threadIdx.x;
    const int bq  = blockIdx.x / 5;     // batch pair: batches {2bq, 2bq+1}
    const int j   = blockIdx.x % 5;     // a-pair: a in {2j, 2j+1}

    // ---- segment increments for both batches ----
    for (int idx = tid; idx < 2 * NSEG * DCH; idx += THREADS) {
        int bsel = idx / (NSEG * DCH);
        int r    = idx % (NSEG * DCH);
        int c = r / NSEG, t = r % NSEG;
        const float* pb = path + (2 * bq + bsel) * (DCH * LEN) + c * LEN;
        sdA[bsel][t * APAD + c] = pb[t + 1] - pb[t];
    }
    __syncthreads();

    // ---- thread decode: 8 groups of 100 ----
    const int g     = tid / 100;        // 0..7
    const int bc    = tid % 100;
    const int bsel  = g >> 2;           // batch select
    const int a_loc = (g >> 1) & 1;     // a = 2j + a_loc
    const int half  = g & 1;            // d-halfset: d = 2*i + half
    const int a     = 2 * j + a_loc;
    const int hb    = bc / 10;
    const int hc    = bc % 10;

    float s1 = 0.f, s2 = 0.f, s3 = 0.f;   // private S1[a], S2[ab], S3[abc]
    float s4[5];                           // S4[abc, 2i+half]
    ull   s5[5][5];                        // [i][e-pair p]
#pragma unroll
    for (int i = 0; i < 5; ++i) {
        s4[i] = 0.f;
#pragma unroll
        for (int p = 0; p < 5; ++p) s5[i][p] = 0ull;
    }

    const float* dl = sdA[bsel];
    for (int t = 0; t < NSEG; ++t, dl += APAD) {
        float4 v0 = *(const float4*)dl;         // δ0..δ3
        float4 v1 = *(const float4*)(dl + 4);   // δ4..δ7
        float2 v2 = *(const float2*)(dl + 8);   // δ8, δ9
        float da = dl[a], db = dl[hb], dc = dl[hc];

        // Horner chains + private state update
        float P1 = fmaf(da, 1.f / 120.f, s1 * (1.f / 24.f));
        float P2 = fmaf(db, P1, s2 * (1.f / 6.f));
        float P3 = fmaf(dc, P2, s3 * 0.5f);
        float Q1 = fmaf(da, 1.f / 24.f, s1 * (1.f / 6.f));
        float Q2 = fmaf(db, Q1, s2 * 0.5f);
        float Y3 = fmaf(dc, Q2, s3);
        float Z1 = fmaf(da, 1.f / 6.f, s1 * 0.5f);
        float Z2 = fmaf(db, Z1, s2);
        s3 = fmaf(dc, Z2, s3);
        float W1 = fmaf(da, 0.5f, s1);
        s2 = fmaf(db, W1, s2);
        s1 += da;

        // e-pairs (adjacent channels)
        ull ep[5];
        ep[0] = pk(v0.x, v0.y);
        ep[1] = pk(v0.z, v0.w);
        ep[2] = pk(v1.x, v1.y);
        ep[3] = pk(v1.z, v1.w);
        ep[4] = pk(v2.x, v2.y);

        // this thread's 5 d-values (interleaved split -> SELs)
        float dloc[5];
        dloc[0] = half ? v0.y : v0.x;
        dloc[1] = half ? v0.w : v0.z;
        dloc[2] = half ? v1.y : v1.x;
        dloc[3] = half ? v1.w : v1.z;
        dloc[4] = half ? v2.y : v2.x;

#pragma unroll
        for (int i = 0; i < 5; ++i) {
            float X = fmaf(dloc[i], P3, s4[i]);     // X4[abc,d]
            s4[i]   = fmaf(dloc[i], Y3, s4[i]);     // S4 += Y3*δd
            ull X2  = pk(X, X);
#pragma unroll
            for (int p = 0; p < 5; ++p)
                s5[i][p] = ffma2(X2, ep[p], s5[i][p]);   // S5 += X4*δe
        }
    }

    // ---- epilogue ----
    float* orow = out + (size_t)(2 * bq + bsel) * ROW;
    const int abc = a * 100 + bc;
    if (half == 0) {
        if (bc == 0) orow[a] = s1;
        if (hc == 0) orow[10 + a * 10 + hb] = s2;
        orow[110 + abc] = s3;
    }
    ull* o5 = (ull*)(orow + 11110);   // 8B-aligned: 11110*4 % 8 == 0
#pragma unroll
    for (int i = 0; i < 5; ++i) {
        int abcd = abc * 10 + 2 * i + half;
        orow[1110 + abcd] = s4[i];
#pragma unroll
        for (int p = 0; p < 5; ++p) o5[abcd * 5 + p] = s5[i][p];
    }
}

extern "C" void kernel_launch(void* const* d_in, const int* in_sizes, int n_in,
                              void* d_out, int out_size) {
    const float* path = (const float*)d_in[0];  // (256, 10, 128) fp32
    float* out = (float*)d_out;                 // (256, 111110) fp32
    sig_kernel<<<(NB / 2) * 5, THREADS>>>(path, out);
}

// round 11
// speedup vs baseline: 1.8188x; 1.5747x over previous
#include <cuda_runtime.h>

// Depth-5 path signature, B=256, d=10, L=128 (127 segments).
// Output row: [S1(10) | S2(100) | S3(1000) | S4(10000) | S5(100000)] = 111110 floats.
//
// Chen recurrence with rank-1 segment tensors (increment δ):
//   P3[abc] = S3/2 + δc*(S2/6 + δb*(S1/24 + δa/120))
//   Y3[abc] = S3   + δc*(S2/2 + δb*(S1/6  + δa/24))
//   X4[abcd] = S4[abcd] + δd*P3[abc];  S4 += Y3 ⊗ δ;  S5 += X4 ⊗ δ
//   S3 += δc*(S2 + δb*(S1/2 + δa/6));  S2 += δb*(S1 + δa/2);  S1 += δ
//
// R11: R3's proven 80-reg loop body (5 interleaved d-columns/thread, 25 packed
// S5 f32x2 + 5 S4 scalars, zero barriers) with fixed geometry:
//   CTA = 256 threads (8 FULL warps), 8 CTAs per batch covering the 2000
//   (half, abc) units; launch_bounds(256,3) -> reg cap 85 -> granule 80 =
//   exactly the natural allocation (NO spill), 24 warps/SM (R3: 21),
//   dead lanes 2.3% (R3: 10.7%), grid 2048 -> 4.6 waves (R3: 5.8).

#define NB 256
#define DCH 10
#define LEN 128
#define NSEG 127
#define THREADS 256
#define CTAS_PER_B 8
#define UNITS 2000          // (half, abc) units per batch
#define ROW 111110
#define APAD 12             // sdA row stride: 48B rows, 16B-aligned

typedef unsigned long long ull;

__device__ __forceinline__ ull pk(float lo, float hi) {
    ull r;
    asm("mov.b64 %0, {%1, %2};" : "=l"(r) : "f"(lo), "f"(hi));
    return r;
}
__device__ __forceinline__ ull ffma2(ull a, ull b, ull c) {
    ull d;
    asm("fma.rn.f32x2 %0, %1, %2, %3;" : "=l"(d) : "l"(a), "l"(b), "l"(c));
    return d;
}

__global__ __launch_bounds__(THREADS, 3)
void sig_kernel(const float* __restrict__ path, float* __restrict__ out) {
    __shared__ __align__(16) float sdA[NSEG * APAD];   // [t][c]

    const int tid = threadIdx.x;
    const int b   = blockIdx.x / CTAS_PER_B;
    const int k   = blockIdx.x % CTAS_PER_B;

    // ---- segment increments (coalesced over t) ----
    const float* pb = path + b * (DCH * LEN);
    for (int idx = tid; idx < NSEG * DCH; idx += THREADS) {
        int c = idx / NSEG, t = idx % NSEG;
        sdA[t * APAD + c] = pb[c * LEN + t + 1] - pb[c * LEN + t];
    }
    __syncthreads();

    // ---- unit decode: u = (half, abc) flattened over the whole batch ----
    const int u = k * THREADS + tid;
    if (u >= UNITS) return;             // only 48 threads of the last CTA per batch
    const int half = u / 1000;          // d-halfset: d = 2*i + half
    const int abc  = u % 1000;
    const int a    = abc / 100;
    const int bc   = abc % 100;
    const int hb   = bc / 10;
    const int hc   = bc % 10;

    float s1 = 0.f, s2 = 0.f, s3 = 0.f;   // private S1[a], S2[ab], S3[abc]
    float s4[5];                           // S4[abc, 2i+half]
    ull   s5[5][5];                        // [i][e-pair p]
#pragma unroll
    for (int i = 0; i < 5; ++i) {
        s4[i] = 0.f;
#pragma unroll
        for (int p = 0; p < 5; ++p) s5[i][p] = 0ull;
    }

    const float* dl = sdA;
    for (int t = 0; t < NSEG; ++t, dl += APAD) {
        float4 v0 = *(const float4*)dl;         // δ0..δ3 (broadcast)
        float4 v1 = *(const float4*)(dl + 4);   // δ4..δ7
        float2 v2 = *(const float2*)(dl + 8);   // δ8, δ9
        float da = dl[a], db = dl[hb], dc = dl[hc];

        // Horner chains + private state update
        float P1 = fmaf(da, 1.f / 120.f, s1 * (1.f / 24.f));
        float P2 = fmaf(db, P1, s2 * (1.f / 6.f));
        float P3 = fmaf(dc, P2, s3 * 0.5f);
        float Q1 = fmaf(da, 1.f / 24.f, s1 * (1.f / 6.f));
        float Q2 = fmaf(db, Q1, s2 * 0.5f);
        float Y3 = fmaf(dc, Q2, s3);
        float Z1 = fmaf(da, 1.f / 6.f, s1 * 0.5f);
        float Z2 = fmaf(db, Z1, s2);
        s3 = fmaf(dc, Z2, s3);
        float W1 = fmaf(da, 0.5f, s1);
        s2 = fmaf(db, W1, s2);
        s1 += da;

        // e-pairs (adjacent channels), register pairs from the vector loads
        ull ep[5];
        ep[0] = pk(v0.x, v0.y);
        ep[1] = pk(v0.z, v0.w);
        ep[2] = pk(v1.x, v1.y);
        ep[3] = pk(v1.z, v1.w);
        ep[4] = pk(v2.x, v2.y);

        // this thread's 5 d-values (interleaved split -> SELs)
        float dloc[5];
        dloc[0] = half ? v0.y : v0.x;
        dloc[1] = half ? v0.w : v0.z;
        dloc[2] = half ? v1.y : v1.x;
        dloc[3] = half ? v1.w : v1.z;
        dloc[4] = half ? v2.y : v2.x;

#pragma unroll
        for (int i = 0; i < 5; ++i) {
            float X = fmaf(dloc[i], P3, s4[i]);     // X4[abc,d]
            s4[i]   = fmaf(dloc[i], Y3, s4[i]);     // S4 += Y3*δd
            ull X2  = pk(X, X);
#pragma unroll
            for (int p = 0; p < 5; ++p)
                s5[i][p] = ffma2(X2, ep[p], s5[i][p]);   // S5[abc,d,·] += X4*δe
        }
    }

    // ---- epilogue ----
    float* orow = out + (size_t)b * ROW;
    if (half == 0) {
        if (bc == 0) orow[a] = s1;
        if (hc == 0) orow[10 + a * 10 + hb] = s2;
        orow[110 + abc] = s3;
    }
    ull* o5 = (ull*)(orow + 11110);   // 8B-aligned: 11110*4 % 8 == 0
#pragma unroll
    for (int i = 0; i < 5; ++i) {
        int abcd = abc * 10 + 2 * i + half;
        orow[1110 + abcd] = s4[i];
#pragma unroll
        for (int p = 0; p < 5; ++p) o5[abcd * 5 + p] = s5[i][p];
    }
}

extern "C" void kernel_launch(void* const* d_in, const int* in_sizes, int n_in,
                              void* d_out, int out_size) {
    const float* path = (const float*)d_in[0];  // (256, 10, 128) fp32
    float* out = (float*)d_out;                 // (256, 111110) fp32
    sig_kernel<<<NB * CTAS_PER_B, THREADS>>>(path, out);
}